// round 14
// baseline (speedup 1.0000x reference)
#include <cuda_runtime.h>
#include <cuda_fp16.h>
#include <cstdint>

// Problem constants
#define OUT_F 11008
#define IN_F  4096
#define M_TOT 4096
#define NGROUPS 32

// GEMM tiling: CTA 128(M) x 128(N), BK=64, 128 threads.
// 4 warps as 2(M) x 2(N), warp tile 64x64.  TWO CTAs per SM.
#define MT 128
#define NT 128
#define KT 64
#define NK (IN_F / KT)             // 64
#define STAGES 3
#define A_BYTES 16384              // 128 x 64 fp16
#define B_BYTES 16384              // 128 x 64 fp16
#define STAGE_BYTES (A_BYTES + B_BYTES)       // 32768
#define SMEM_BYTES (STAGES * STAGE_BYTES)     // 98304

// Persistent fp16 operand buffers
__device__ __half g_xh[(size_t)M_TOT * IN_F];     // 32 MB
__device__ __half g_wh[(size_t)OUT_F * IN_F];     // 90 MB

// ---------------------------------------------------------------------------
// helpers
// ---------------------------------------------------------------------------
__device__ __forceinline__ uint32_t smem_u32(const void* p) {
    uint32_t a;
    asm("{ .reg .u64 t; cvta.to.shared.u64 t, %1; cvt.u32.u64 %0, t; }"
        : "=r"(a) : "l"(p));
    return a;
}

__device__ __forceinline__ uint32_t sw128(uint32_t b) {
    return b ^ ((b >> 3) & 0x70);
}

__device__ __forceinline__ void cp16(uint32_t saddr, const void* gaddr) {
    asm volatile("cp.async.cg.shared.global.L2::128B [%0], [%1], 16;"
                 :: "r"(saddr), "l"(gaddr));
}

#define CP_COMMIT()  asm volatile("cp.async.commit_group;" ::: "memory")
#define CP_WAIT1()   asm volatile("cp.async.wait_group 1;"  ::: "memory")

__device__ __forceinline__ void ldsm_x4(uint32_t& r0, uint32_t& r1,
                                        uint32_t& r2, uint32_t& r3, uint32_t addr) {
    asm volatile("ldmatrix.sync.aligned.m8n8.x4.shared.b16 {%0,%1,%2,%3}, [%4];"
                 : "=r"(r0), "=r"(r1), "=r"(r2), "=r"(r3) : "r"(addr));
}

__device__ __forceinline__ void mma16816(float* d, const uint32_t* a,
                                         uint32_t b0, uint32_t b1) {
    asm volatile(
        "mma.sync.aligned.m16n8k16.row.col.f32.f16.f16.f32 "
        "{%0,%1,%2,%3}, {%4,%5,%6,%7}, {%8,%9}, {%0,%1,%2,%3};"
        : "+f"(d[0]), "+f"(d[1]), "+f"(d[2]), "+f"(d[3])
        : "r"(a[0]), "r"(a[1]), "r"(a[2]), "r"(a[3]), "r"(b0), "r"(b1));
}

__device__ __forceinline__ void stcs2(float* p, float2 v) {
    asm volatile("st.global.cs.v2.f32 [%0], {%1, %2};"
                 :: "l"(p), "f"(v.x), "f"(v.y) : "memory");
}

// ---------------------------------------------------------------------------
// Merged prepass: 512-thread blocks, 16 elems/thread.
// ---------------------------------------------------------------------------
#define CVT_BLOCKS 2048
#define DQ_BLOCKS  5504

__global__ void __launch_bounds__(512)
k_prepass(const float* __restrict__ x,
          const int* __restrict__ q,
          const float* __restrict__ s) {
    if (blockIdx.x < CVT_BLOCKS) {
        size_t base = ((size_t)blockIdx.x * 512 + threadIdx.x) * 16;
#pragma unroll
        for (int h = 0; h < 2; h++) {
            size_t i = base + h * 8;
            float4 a = *(const float4*)(x + i);
            float4 b = *(const float4*)(x + i + 4);
            __half v[8];
            v[0] = __float2half_rn(a.x); v[1] = __float2half_rn(a.y);
            v[2] = __float2half_rn(a.z); v[3] = __float2half_rn(a.w);
            v[4] = __float2half_rn(b.x); v[5] = __float2half_rn(b.y);
            v[6] = __float2half_rn(b.z); v[7] = __float2half_rn(b.w);
            *(uint4*)(g_xh + i) = *(const uint4*)v;
        }
    } else {
        size_t t = (size_t)(blockIdx.x - CVT_BLOCKS) * 512 + threadIdx.x;
        int o  = (int)(t >> 8);            // 256 chunks per out row
        int i0 = (int)(t & 255) << 4;
        float sc = s[o * NGROUPS + (i0 >> 7)];
        const int4* qp = (const int4*)(q + (size_t)o * IN_F + i0);
#pragma unroll
        for (int h = 0; h < 2; h++) {
            int4 q0 = qp[h * 2], q1 = qp[h * 2 + 1];
            __half v[8];
            v[0] = __float2half_rn((float)q0.x * sc);
            v[1] = __float2half_rn((float)q0.y * sc);
            v[2] = __float2half_rn((float)q0.z * sc);
            v[3] = __float2half_rn((float)q0.w * sc);
            v[4] = __float2half_rn((float)q1.x * sc);
            v[5] = __float2half_rn((float)q1.y * sc);
            v[6] = __float2half_rn((float)q1.z * sc);
            v[7] = __float2half_rn((float)q1.w * sc);
            *(uint4*)(g_wh + (size_t)o * IN_F + i0 + h * 8) = *(const uint4*)v;
        }
    }
}

// ---------------------------------------------------------------------------
// GEMM: out[m,n] = sum_k xh[m,k]*wh[n,k] + bias[n]
// CTA 128x128, 128 threads, 4 warps (2x2 of 64x64), 3-stage cp.async,
// 2 CTAs per SM.  vs R13: inside k16==0, the 8 ldsm issue FIRST, then the
// cp.async bundle for stage kc+2 (+commit), then mma — the ldsm smem
// latency covers the cp issue burst, restarting the tensor pipe sooner.
// ---------------------------------------------------------------------------
__global__ void __launch_bounds__(128, 2)
k_gemm(const float* __restrict__ bias, float* __restrict__ out) {
    extern __shared__ char smem[];
    const uint32_t sb = smem_u32(smem);

    const int tid = threadIdx.x;
    const int wid = tid >> 5, lid = tid & 31;
    const int wm = wid & 1;          // 2 warp rows  -> 64 M each
    const int wn = wid >> 1;         // 2 warp cols  -> 64 N each
    const int mB = blockIdx.x, nB = blockIdx.y;

    const __half* Ag = g_xh + (size_t)(mB * MT) * IN_F;
    const __half* Bg = g_wh + (size_t)(nB * NT) * IN_F;

    // 1024 16B chunks per tile per stage, 8 per thread (cached coords)
    uint32_t c_sw[8], c_go[8];
#pragma unroll
    for (int i = 0; i < 8; i++) {
        int idx = tid + i * 128;
        int r = idx >> 3, c = idx & 7;
        c_sw[i] = sw128((uint32_t)(r * 128 + c * 16));
        c_go[i] = (uint32_t)(r * IN_F + c * 8);
    }

    auto load_stage = [&](int slot, int kc) {
        const uint32_t abase = sb + slot * STAGE_BYTES;
        const uint32_t bbase = abase + A_BYTES;
        const __half* ga = Ag + kc * KT;
        const __half* gb = Bg + kc * KT;
#pragma unroll
        for (int i = 0; i < 8; i++) cp16(abase + c_sw[i], ga + c_go[i]);
#pragma unroll
        for (int i = 0; i < 8; i++) cp16(bbase + c_sw[i], gb + c_go[i]);
    };

    load_stage(0, 0); CP_COMMIT();
    load_stage(1, 1); CP_COMMIT();

    // preload bias (keeps epilogue store-only)
    const int c0 = nB * NT + wn * 64 + (lid & 3) * 2;
    float2 bre[8];
#pragma unroll
    for (int nt = 0; nt < 8; nt++) {
        bre[nt].x = __ldg(bias + c0 + nt * 8);
        bre[nt].y = __ldg(bias + c0 + nt * 8 + 1);
    }

    // ldmatrix lane address components
    const int la_row = wm * 64 + (lid & 15);                       // + mt*16
    const int la_kh  = (lid >> 4) * 8;
    const int lb_row = wn * 64 + ((lid & 7) | ((lid & 16) >> 1));  // + nt2*16
    const int lb_kh  = (lid & 8);

    float acc[4][8][4];
#pragma unroll
    for (int mt = 0; mt < 4; mt++)
#pragma unroll
        for (int nt = 0; nt < 8; nt++)
#pragma unroll
            for (int e = 0; e < 4; e++) acc[mt][nt][e] = 0.0f;

#pragma unroll 3
    for (int kc = 0; kc < NK; kc++) {
        const int slot = kc % STAGES;          // const per unrolled copy
        CP_WAIT1();        // this thread's group kc complete
        __syncthreads();   // ...and everyone else's (publishes all smem writes)

        const uint32_t abase = sb + slot * STAGE_BYTES;
        const uint32_t bbase = abase + A_BYTES;

#pragma unroll
        for (int k16 = 0; k16 < 4; k16++) {
            const int khA = k16 * 16 + la_kh;
            const int khB = k16 * 16 + lb_kh;

            uint32_t a[4][4];
#pragma unroll
            for (int mt = 0; mt < 4; mt++) {
                uint32_t boff = (uint32_t)((la_row + mt * 16) * 128 + khA * 2);
                ldsm_x4(a[mt][0], a[mt][1], a[mt][2], a[mt][3], abase + sw128(boff));
            }
            uint32_t b[8][2];
#pragma unroll
            for (int nt2 = 0; nt2 < 4; nt2++) {
                uint32_t boff = (uint32_t)((lb_row + nt2 * 16) * 128 + khB * 2);
                uint32_t r0, r1, r2, r3;
                ldsm_x4(r0, r1, r2, r3, bbase + sw128(boff));
                b[nt2 * 2][0] = r0;     b[nt2 * 2][1] = r1;
                b[nt2 * 2 + 1][0] = r2; b[nt2 * 2 + 1][1] = r3;
            }

            // k16==0: issue next-stage cp.async while the ldsm results are
            // in flight (slot(kc+2) == slot(kc-1); its readers finished
            // before the barrier above). Commit immediately after.
            if (k16 == 0) {
                if (kc + 2 < NK) {
                    int ns = slot + 2; if (ns >= STAGES) ns -= STAGES;
                    load_stage(ns, kc + 2);
                }
                CP_COMMIT();   // uniform group count (may be empty)
            }

#pragma unroll
            for (int mt = 0; mt < 4; mt++)
#pragma unroll
                for (int nt = 0; nt < 8; nt++)
                    mma16816(acc[mt][nt], a[mt], b[nt][0], b[nt][1]);
        }
    }

    // epilogue: m16n8 d-frag: rows lane/4 (+8), cols (lane%4)*2 (+1)
    // Streaming stores (.cs): output is never re-read; keep operands in L2.
    const int r0 = mB * MT + wm * 64 + (lid >> 2);

#pragma unroll
    for (int nt = 0; nt < 8; nt++) {
        const int col = c0 + nt * 8;
#pragma unroll
        for (int mt = 0; mt < 4; mt++) {
            float* p0 = out + (size_t)(r0 + mt * 16) * OUT_F + col;
            float* p1 = p0 + 8 * OUT_F;
            float2 v0 = { acc[mt][nt][0] + bre[nt].x, acc[mt][nt][1] + bre[nt].y };
            float2 v1 = { acc[mt][nt][2] + bre[nt].x, acc[mt][nt][3] + bre[nt].y };
            stcs2(p0, v0);
            stcs2(p1, v1);
        }
    }
}

// ---------------------------------------------------------------------------
// Launch
// ---------------------------------------------------------------------------
extern "C" void kernel_launch(void* const* d_in, const int* in_sizes, int n_in,
                              void* d_out, int out_size) {
    (void)in_sizes; (void)n_in; (void)out_size;
    const float* x    = (const float*)d_in[0];
    const int*   qw   = (const int*)d_in[1];
    const float* sc   = (const float*)d_in[2];
    const float* bias = (const float*)d_in[3];
    float* out = (float*)d_out;

    k_prepass<<<CVT_BLOCKS + DQ_BLOCKS, 512>>>(x, qw, sc);

    cudaFuncSetAttribute(k_gemm, cudaFuncAttributeMaxDynamicSharedMemorySize, SMEM_BYTES);
    dim3 grid(M_TOT / MT, OUT_F / NT);   // 32 x 86 = 2752 CTAs, 2 per SM
    k_gemm<<<grid, 128, SMEM_BYTES>>>(bias, out);
}

// round 15
// speedup vs baseline: 1.0503x; 1.0503x over previous
#include <cuda_runtime.h>
#include <cuda_fp16.h>
#include <cstdint>

// Problem constants
#define OUT_F 11008
#define IN_F  4096
#define M_TOT 4096
#define NGROUPS 32

// GEMM tiling: CTA 128(M) x 128(N), BK=64, 128 threads.
// 4 warps as 2(M) x 2(N), warp tile 64x64.  TWO CTAs per SM.
#define MT 128
#define NT 128
#define KT 64
#define NK (IN_F / KT)             // 64
#define STAGES 3
#define A_BYTES 16384              // 128 x 64 fp16
#define B_BYTES 16384              // 128 x 64 fp16
#define STAGE_BYTES (A_BYTES + B_BYTES)       // 32768
#define SMEM_BYTES (STAGES * STAGE_BYTES)     // 98304

// Persistent fp16 operand buffers
__device__ __half g_xh[(size_t)M_TOT * IN_F];     // 32 MB
__device__ __half g_wh[(size_t)OUT_F * IN_F];     // 90 MB

// ---------------------------------------------------------------------------
// helpers
// ---------------------------------------------------------------------------
__device__ __forceinline__ uint32_t smem_u32(const void* p) {
    uint32_t a;
    asm("{ .reg .u64 t; cvta.to.shared.u64 t, %1; cvt.u32.u64 %0, t; }"
        : "=r"(a) : "l"(p));
    return a;
}

__device__ __forceinline__ uint32_t sw128(uint32_t b) {
    return b ^ ((b >> 3) & 0x70);
}

__device__ __forceinline__ void cp16(uint32_t saddr, const void* gaddr) {
    asm volatile("cp.async.cg.shared.global.L2::128B [%0], [%1], 16;"
                 :: "r"(saddr), "l"(gaddr));
}

#define CP_COMMIT()  asm volatile("cp.async.commit_group;" ::: "memory")
#define CP_WAIT1()   asm volatile("cp.async.wait_group 1;"  ::: "memory")

__device__ __forceinline__ void ldsm_x4(uint32_t& r0, uint32_t& r1,
                                        uint32_t& r2, uint32_t& r3, uint32_t addr) {
    asm volatile("ldmatrix.sync.aligned.m8n8.x4.shared.b16 {%0,%1,%2,%3}, [%4];"
                 : "=r"(r0), "=r"(r1), "=r"(r2), "=r"(r3) : "r"(addr));
}

__device__ __forceinline__ void mma16816(float* d, const uint32_t* a,
                                         uint32_t b0, uint32_t b1) {
    asm volatile(
        "mma.sync.aligned.m16n8k16.row.col.f32.f16.f16.f32 "
        "{%0,%1,%2,%3}, {%4,%5,%6,%7}, {%8,%9}, {%0,%1,%2,%3};"
        : "+f"(d[0]), "+f"(d[1]), "+f"(d[2]), "+f"(d[3])
        : "r"(a[0]), "r"(a[1]), "r"(a[2]), "r"(a[3]), "r"(b0), "r"(b1));
}

__device__ __forceinline__ void stcs2(float* p, float2 v) {
    asm volatile("st.global.cs.v2.f32 [%0], {%1, %2};"
                 :: "l"(p), "f"(v.x), "f"(v.y) : "memory");
}

// ---------------------------------------------------------------------------
// Merged prepass: 512-thread blocks, 16 elems/thread.
// ---------------------------------------------------------------------------
#define CVT_BLOCKS 2048
#define DQ_BLOCKS  5504

__global__ void __launch_bounds__(512)
k_prepass(const float* __restrict__ x,
          const int* __restrict__ q,
          const float* __restrict__ s) {
    if (blockIdx.x < CVT_BLOCKS) {
        size_t base = ((size_t)blockIdx.x * 512 + threadIdx.x) * 16;
#pragma unroll
        for (int h = 0; h < 2; h++) {
            size_t i = base + h * 8;
            float4 a = *(const float4*)(x + i);
            float4 b = *(const float4*)(x + i + 4);
            __half v[8];
            v[0] = __float2half_rn(a.x); v[1] = __float2half_rn(a.y);
            v[2] = __float2half_rn(a.z); v[3] = __float2half_rn(a.w);
            v[4] = __float2half_rn(b.x); v[5] = __float2half_rn(b.y);
            v[6] = __float2half_rn(b.z); v[7] = __float2half_rn(b.w);
            *(uint4*)(g_xh + i) = *(const uint4*)v;
        }
    } else {
        size_t t = (size_t)(blockIdx.x - CVT_BLOCKS) * 512 + threadIdx.x;
        int o  = (int)(t >> 8);            // 256 chunks per out row
        int i0 = (int)(t & 255) << 4;
        float sc = s[o * NGROUPS + (i0 >> 7)];
        const int4* qp = (const int4*)(q + (size_t)o * IN_F + i0);
#pragma unroll
        for (int h = 0; h < 2; h++) {
            int4 q0 = qp[h * 2], q1 = qp[h * 2 + 1];
            __half v[8];
            v[0] = __float2half_rn((float)q0.x * sc);
            v[1] = __float2half_rn((float)q0.y * sc);
            v[2] = __float2half_rn((float)q0.z * sc);
            v[3] = __float2half_rn((float)q0.w * sc);
            v[4] = __float2half_rn((float)q1.x * sc);
            v[5] = __float2half_rn((float)q1.y * sc);
            v[6] = __float2half_rn((float)q1.z * sc);
            v[7] = __float2half_rn((float)q1.w * sc);
            *(uint4*)(g_wh + (size_t)o * IN_F + i0 + h * 8) = *(const uint4*)v;
        }
    }
}

// ---------------------------------------------------------------------------
// GEMM: out[m,n] = sum_k xh[m,k]*wh[n,k] + bias[n]
// CTA 128x128, 128 threads, 4 warps (2x2 of 64x64), 3-stage cp.async,
// 2 CTAs per SM.  R13-winning structure: WAIT -> sync -> bulk load issue
// -> commit -> compute; kc loop unrolled x6 (multiple of STAGES, so slot
// stays compile-time const per copy; wider cross-iteration scheduling
// window for ptxas at fixed register footprint).
// ---------------------------------------------------------------------------
__global__ void __launch_bounds__(128, 2)
k_gemm(const float* __restrict__ bias, float* __restrict__ out) {
    extern __shared__ char smem[];
    const uint32_t sb = smem_u32(smem);

    const int tid = threadIdx.x;
    const int wid = tid >> 5, lid = tid & 31;
    const int wm = wid & 1;          // 2 warp rows  -> 64 M each
    const int wn = wid >> 1;         // 2 warp cols  -> 64 N each
    const int mB = blockIdx.x, nB = blockIdx.y;

    const __half* Ag = g_xh + (size_t)(mB * MT) * IN_F;
    const __half* Bg = g_wh + (size_t)(nB * NT) * IN_F;

    // 1024 16B chunks per tile per stage, 8 per thread (cached coords)
    uint32_t c_sw[8], c_go[8];
#pragma unroll
    for (int i = 0; i < 8; i++) {
        int idx = tid + i * 128;
        int r = idx >> 3, c = idx & 7;
        c_sw[i] = sw128((uint32_t)(r * 128 + c * 16));
        c_go[i] = (uint32_t)(r * IN_F + c * 8);
    }

    auto load_stage = [&](int slot, int kc) {
        const uint32_t abase = sb + slot * STAGE_BYTES;
        const uint32_t bbase = abase + A_BYTES;
        const __half* ga = Ag + kc * KT;
        const __half* gb = Bg + kc * KT;
#pragma unroll
        for (int i = 0; i < 8; i++) cp16(abase + c_sw[i], ga + c_go[i]);
#pragma unroll
        for (int i = 0; i < 8; i++) cp16(bbase + c_sw[i], gb + c_go[i]);
    };

    load_stage(0, 0); CP_COMMIT();
    load_stage(1, 1); CP_COMMIT();

    // preload bias (keeps epilogue store-only)
    const int c0 = nB * NT + wn * 64 + (lid & 3) * 2;
    float2 bre[8];
#pragma unroll
    for (int nt = 0; nt < 8; nt++) {
        bre[nt].x = __ldg(bias + c0 + nt * 8);
        bre[nt].y = __ldg(bias + c0 + nt * 8 + 1);
    }

    // ldmatrix lane address components
    const int la_row = wm * 64 + (lid & 15);                       // + mt*16
    const int la_kh  = (lid >> 4) * 8;
    const int lb_row = wn * 64 + ((lid & 7) | ((lid & 16) >> 1));  // + nt2*16
    const int lb_kh  = (lid & 8);

    float acc[4][8][4];
#pragma unroll
    for (int mt = 0; mt < 4; mt++)
#pragma unroll
        for (int nt = 0; nt < 8; nt++)
#pragma unroll
            for (int e = 0; e < 4; e++) acc[mt][nt][e] = 0.0f;

#pragma unroll 6
    for (int kc = 0; kc < NK; kc++) {
        const int slot = kc % STAGES;          // const per unrolled copy
        CP_WAIT1();        // this thread's group kc complete
        __syncthreads();   // ...and everyone else's (publishes all smem writes)

        if (kc + 2 < NK) {
            int ns = slot + 2; if (ns >= STAGES) ns -= STAGES;
            load_stage(ns, kc + 2);
        }
        CP_COMMIT();   // uniform group count (may be empty)

        const uint32_t abase = sb + slot * STAGE_BYTES;
        const uint32_t bbase = abase + A_BYTES;

#pragma unroll
        for (int k16 = 0; k16 < 4; k16++) {
            const int khA = k16 * 16 + la_kh;
            const int khB = k16 * 16 + lb_kh;

            uint32_t a[4][4];
#pragma unroll
            for (int mt = 0; mt < 4; mt++) {
                uint32_t boff = (uint32_t)((la_row + mt * 16) * 128 + khA * 2);
                ldsm_x4(a[mt][0], a[mt][1], a[mt][2], a[mt][3], abase + sw128(boff));
            }
            uint32_t b[8][2];
#pragma unroll
            for (int nt2 = 0; nt2 < 4; nt2++) {
                uint32_t boff = (uint32_t)((lb_row + nt2 * 16) * 128 + khB * 2);
                uint32_t r0, r1, r2, r3;
                ldsm_x4(r0, r1, r2, r3, bbase + sw128(boff));
                b[nt2 * 2][0] = r0;     b[nt2 * 2][1] = r1;
                b[nt2 * 2 + 1][0] = r2; b[nt2 * 2 + 1][1] = r3;
            }
#pragma unroll
            for (int mt = 0; mt < 4; mt++)
#pragma unroll
                for (int nt = 0; nt < 8; nt++)
                    mma16816(acc[mt][nt], a[mt], b[nt][0], b[nt][1]);
        }
    }

    // epilogue: m16n8 d-frag: rows lane/4 (+8), cols (lane%4)*2 (+1)
    // Streaming stores (.cs): output is never re-read; keep operands in L2.
    const int r0 = mB * MT + wm * 64 + (lid >> 2);

#pragma unroll
    for (int nt = 0; nt < 8; nt++) {
        const int col = c0 + nt * 8;
#pragma unroll
        for (int mt = 0; mt < 4; mt++) {
            float* p0 = out + (size_t)(r0 + mt * 16) * OUT_F + col;
            float* p1 = p0 + 8 * OUT_F;
            float2 v0 = { acc[mt][nt][0] + bre[nt].x, acc[mt][nt][1] + bre[nt].y };
            float2 v1 = { acc[mt][nt][2] + bre[nt].x, acc[mt][nt][3] + bre[nt].y };
            stcs2(p0, v0);
            stcs2(p1, v1);
        }
    }
}

// ---------------------------------------------------------------------------
// Launch
// ---------------------------------------------------------------------------
extern "C" void kernel_launch(void* const* d_in, const int* in_sizes, int n_in,
                              void* d_out, int out_size) {
    (void)in_sizes; (void)n_in; (void)out_size;
    const float* x    = (const float*)d_in[0];
    const int*   qw   = (const int*)d_in[1];
    const float* sc   = (const float*)d_in[2];
    const float* bias = (const float*)d_in[3];
    float* out = (float*)d_out;

    k_prepass<<<CVT_BLOCKS + DQ_BLOCKS, 512>>>(x, qw, sc);

    cudaFuncSetAttribute(k_gemm, cudaFuncAttributeMaxDynamicSharedMemorySize, SMEM_BYTES);
    dim3 grid(M_TOT / MT, OUT_F / NT);   // 32 x 86 = 2752 CTAs, 2 per SM
    k_gemm<<<grid, 128, SMEM_BYTES>>>(bias, out);
}

// round 16
// speedup vs baseline: 1.0515x; 1.0012x over previous
#include <cuda_runtime.h>
#include <cuda_fp16.h>
#include <cstdint>

// Problem constants
#define OUT_F 11008
#define IN_F  4096
#define M_TOT 4096
#define NGROUPS 32

// GEMM tiling: CTA 128(M) x 128(N), BK=64, 128 threads.
// 4 warps as 2(M) x 2(N), warp tile 64x64.  TWO CTAs per SM.
#define MT 128
#define NT 128
#define KT 64
#define NK (IN_F / KT)             // 64
#define STAGES 3
#define A_BYTES 16384              // 128 x 64 fp16
#define B_BYTES 16384              // 128 x 64 fp16
#define STAGE_BYTES (A_BYTES + B_BYTES)       // 32768
#define SMEM_BYTES (STAGES * STAGE_BYTES)     // 98304

// Persistent fp16 operand buffers
__device__ __half g_xh[(size_t)M_TOT * IN_F];     // 32 MB
__device__ __half g_wh[(size_t)OUT_F * IN_F];     // 90 MB

// ---------------------------------------------------------------------------
// helpers
// ---------------------------------------------------------------------------
__device__ __forceinline__ uint32_t smem_u32(const void* p) {
    uint32_t a;
    asm("{ .reg .u64 t; cvta.to.shared.u64 t, %1; cvt.u32.u64 %0, t; }"
        : "=r"(a) : "l"(p));
    return a;
}

__device__ __forceinline__ uint32_t sw128(uint32_t b) {
    return b ^ ((b >> 3) & 0x70);
}

__device__ __forceinline__ void cp16(uint32_t saddr, const void* gaddr) {
    asm volatile("cp.async.cg.shared.global.L2::128B [%0], [%1], 16;"
                 :: "r"(saddr), "l"(gaddr));
}

#define CP_COMMIT()  asm volatile("cp.async.commit_group;" ::: "memory")
#define CP_WAIT1()   asm volatile("cp.async.wait_group 1;"  ::: "memory")

__device__ __forceinline__ void ldsm_x4(uint32_t& r0, uint32_t& r1,
                                        uint32_t& r2, uint32_t& r3, uint32_t addr) {
    asm volatile("ldmatrix.sync.aligned.m8n8.x4.shared.b16 {%0,%1,%2,%3}, [%4];"
                 : "=r"(r0), "=r"(r1), "=r"(r2), "=r"(r3) : "r"(addr));
}

__device__ __forceinline__ void mma16816(float* d, const uint32_t* a,
                                         uint32_t b0, uint32_t b1) {
    asm volatile(
        "mma.sync.aligned.m16n8k16.row.col.f32.f16.f16.f32 "
        "{%0,%1,%2,%3}, {%4,%5,%6,%7}, {%8,%9}, {%0,%1,%2,%3};"
        : "+f"(d[0]), "+f"(d[1]), "+f"(d[2]), "+f"(d[3])
        : "r"(a[0]), "r"(a[1]), "r"(a[2]), "r"(a[3]), "r"(b0), "r"(b1));
}

__device__ __forceinline__ void stcs2(float* p, float2 v) {
    asm volatile("st.global.cs.v2.f32 [%0], {%1, %2};"
                 :: "l"(p), "f"(v.x), "f"(v.y) : "memory");
}

// ---------------------------------------------------------------------------
// Merged prepass: 512-thread blocks, 16 elems/thread.
// ---------------------------------------------------------------------------
#define CVT_BLOCKS 2048
#define DQ_BLOCKS  5504

__global__ void __launch_bounds__(512)
k_prepass(const float* __restrict__ x,
          const int* __restrict__ q,
          const float* __restrict__ s) {
    if (blockIdx.x < CVT_BLOCKS) {
        size_t base = ((size_t)blockIdx.x * 512 + threadIdx.x) * 16;
#pragma unroll
        for (int h = 0; h < 2; h++) {
            size_t i = base + h * 8;
            float4 a = *(const float4*)(x + i);
            float4 b = *(const float4*)(x + i + 4);
            __half v[8];
            v[0] = __float2half_rn(a.x); v[1] = __float2half_rn(a.y);
            v[2] = __float2half_rn(a.z); v[3] = __float2half_rn(a.w);
            v[4] = __float2half_rn(b.x); v[5] = __float2half_rn(b.y);
            v[6] = __float2half_rn(b.z); v[7] = __float2half_rn(b.w);
            *(uint4*)(g_xh + i) = *(const uint4*)v;
        }
    } else {
        size_t t = (size_t)(blockIdx.x - CVT_BLOCKS) * 512 + threadIdx.x;
        int o  = (int)(t >> 8);            // 256 chunks per out row
        int i0 = (int)(t & 255) << 4;
        float sc = s[o * NGROUPS + (i0 >> 7)];
        const int4* qp = (const int4*)(q + (size_t)o * IN_F + i0);
#pragma unroll
        for (int h = 0; h < 2; h++) {
            int4 q0 = qp[h * 2], q1 = qp[h * 2 + 1];
            __half v[8];
            v[0] = __float2half_rn((float)q0.x * sc);
            v[1] = __float2half_rn((float)q0.y * sc);
            v[2] = __float2half_rn((float)q0.z * sc);
            v[3] = __float2half_rn((float)q0.w * sc);
            v[4] = __float2half_rn((float)q1.x * sc);
            v[5] = __float2half_rn((float)q1.y * sc);
            v[6] = __float2half_rn((float)q1.z * sc);
            v[7] = __float2half_rn((float)q1.w * sc);
            *(uint4*)(g_wh + (size_t)o * IN_F + i0 + h * 8) = *(const uint4*)v;
        }
    }
}

// ---------------------------------------------------------------------------
// GEMM: out[m,n] = sum_k xh[m,k]*wh[n,k] + bias[n]
// CTA 128x128, 128 threads, 4 warps (2x2 of 64x64), 3-stage cp.async,
// 2 CTAs per SM.  R13-winning structure: WAIT -> sync -> bulk load issue
// -> commit -> compute; kc loop unrolled x6 (multiple of STAGES, so slot
// stays compile-time const per copy; wider cross-iteration scheduling
// window for ptxas at fixed register footprint).
// ---------------------------------------------------------------------------
__global__ void __launch_bounds__(128, 2)
k_gemm(const float* __restrict__ bias, float* __restrict__ out) {
    extern __shared__ char smem[];
    const uint32_t sb = smem_u32(smem);

    const int tid = threadIdx.x;
    const int wid = tid >> 5, lid = tid & 31;
    const int wm = wid & 1;          // 2 warp rows  -> 64 M each
    const int wn = wid >> 1;         // 2 warp cols  -> 64 N each
    const int mB = blockIdx.x, nB = blockIdx.y;

    const __half* Ag = g_xh + (size_t)(mB * MT) * IN_F;
    const __half* Bg = g_wh + (size_t)(nB * NT) * IN_F;

    // 1024 16B chunks per tile per stage, 8 per thread (cached coords)
    uint32_t c_sw[8], c_go[8];
#pragma unroll
    for (int i = 0; i < 8; i++) {
        int idx = tid + i * 128;
        int r = idx >> 3, c = idx & 7;
        c_sw[i] = sw128((uint32_t)(r * 128 + c * 16));
        c_go[i] = (uint32_t)(r * IN_F + c * 8);
    }

    auto load_stage = [&](int slot, int kc) {
        const uint32_t abase = sb + slot * STAGE_BYTES;
        const uint32_t bbase = abase + A_BYTES;
        const __half* ga = Ag + kc * KT;
        const __half* gb = Bg + kc * KT;
#pragma unroll
        for (int i = 0; i < 8; i++) cp16(abase + c_sw[i], ga + c_go[i]);
#pragma unroll
        for (int i = 0; i < 8; i++) cp16(bbase + c_sw[i], gb + c_go[i]);
    };

    load_stage(0, 0); CP_COMMIT();
    load_stage(1, 1); CP_COMMIT();

    // preload bias (keeps epilogue store-only)
    const int c0 = nB * NT + wn * 64 + (lid & 3) * 2;
    float2 bre[8];
#pragma unroll
    for (int nt = 0; nt < 8; nt++) {
        bre[nt].x = __ldg(bias + c0 + nt * 8);
        bre[nt].y = __ldg(bias + c0 + nt * 8 + 1);
    }

    // ldmatrix lane address components
    const int la_row = wm * 64 + (lid & 15);                       // + mt*16
    const int la_kh  = (lid >> 4) * 8;
    const int lb_row = wn * 64 + ((lid & 7) | ((lid & 16) >> 1));  // + nt2*16
    const int lb_kh  = (lid & 8);

    float acc[4][8][4];
#pragma unroll
    for (int mt = 0; mt < 4; mt++)
#pragma unroll
        for (int nt = 0; nt < 8; nt++)
#pragma unroll
            for (int e = 0; e < 4; e++) acc[mt][nt][e] = 0.0f;

#pragma unroll 6
    for (int kc = 0; kc < NK; kc++) {
        const int slot = kc % STAGES;          // const per unrolled copy
        CP_WAIT1();        // this thread's group kc complete
        __syncthreads();   // ...and everyone else's (publishes all smem writes)

        if (kc + 2 < NK) {
            int ns = slot + 2; if (ns >= STAGES) ns -= STAGES;
            load_stage(ns, kc + 2);
        }
        CP_COMMIT();   // uniform group count (may be empty)

        const uint32_t abase = sb + slot * STAGE_BYTES;
        const uint32_t bbase = abase + A_BYTES;

#pragma unroll
        for (int k16 = 0; k16 < 4; k16++) {
            const int khA = k16 * 16 + la_kh;
            const int khB = k16 * 16 + lb_kh;

            uint32_t a[4][4];
#pragma unroll
            for (int mt = 0; mt < 4; mt++) {
                uint32_t boff = (uint32_t)((la_row + mt * 16) * 128 + khA * 2);
                ldsm_x4(a[mt][0], a[mt][1], a[mt][2], a[mt][3], abase + sw128(boff));
            }
            uint32_t b[8][2];
#pragma unroll
            for (int nt2 = 0; nt2 < 4; nt2++) {
                uint32_t boff = (uint32_t)((lb_row + nt2 * 16) * 128 + khB * 2);
                uint32_t r0, r1, r2, r3;
                ldsm_x4(r0, r1, r2, r3, bbase + sw128(boff));
                b[nt2 * 2][0] = r0;     b[nt2 * 2][1] = r1;
                b[nt2 * 2 + 1][0] = r2; b[nt2 * 2 + 1][1] = r3;
            }
#pragma unroll
            for (int mt = 0; mt < 4; mt++)
#pragma unroll
                for (int nt = 0; nt < 8; nt++)
                    mma16816(acc[mt][nt], a[mt], b[nt][0], b[nt][1]);
        }
    }

    // epilogue: m16n8 d-frag: rows lane/4 (+8), cols (lane%4)*2 (+1)
    // Streaming stores (.cs): output is never re-read; keep operands in L2.
    const int r0 = mB * MT + wm * 64 + (lid >> 2);

#pragma unroll
    for (int nt = 0; nt < 8; nt++) {
        const int col = c0 + nt * 8;
#pragma unroll
        for (int mt = 0; mt < 4; mt++) {
            float* p0 = out + (size_t)(r0 + mt * 16) * OUT_F + col;
            float* p1 = p0 + 8 * OUT_F;
            float2 v0 = { acc[mt][nt][0] + bre[nt].x, acc[mt][nt][1] + bre[nt].y };
            float2 v1 = { acc[mt][nt][2] + bre[nt].x, acc[mt][nt][3] + bre[nt].y };
            stcs2(p0, v0);
            stcs2(p1, v1);
        }
    }
}

// ---------------------------------------------------------------------------
// Launch
// ---------------------------------------------------------------------------
extern "C" void kernel_launch(void* const* d_in, const int* in_sizes, int n_in,
                              void* d_out, int out_size) {
    (void)in_sizes; (void)n_in; (void)out_size;
    const float* x    = (const float*)d_in[0];
    const int*   qw   = (const int*)d_in[1];
    const float* sc   = (const float*)d_in[2];
    const float* bias = (const float*)d_in[3];
    float* out = (float*)d_out;

    k_prepass<<<CVT_BLOCKS + DQ_BLOCKS, 512>>>(x, qw, sc);

    cudaFuncSetAttribute(k_gemm, cudaFuncAttributeMaxDynamicSharedMemorySize, SMEM_BYTES);
    dim3 grid(M_TOT / MT, OUT_F / NT);   // 32 x 86 = 2752 CTAs, 2 per SM
    k_gemm<<<grid, 128, SMEM_BYTES>>>(bias, out);
}